// round 11
// baseline (speedup 1.0000x reference)
#include <cuda_runtime.h>
#include <cstdint>

// Problem constants
#define BB 64       // batch
#define KK 4096     // dim_in
#define OO 4096     // dim_out
#define KW 128      // KK/32 bit-words along k
#define OT 16       // output columns per strip
#define NSTRIP (OO / OT)    // 256
#define SLABS  4            // k-split
#define SKW    (KW / SLABS) // 32 kw per slab (1024 k-rows)
#define GRID   (NSTRIP * SLABS)   // 1024 blocks

#define NPACK_BLK    128                          // x-packer blocks (wave-1 safe)
#define PACK_PER_BLK (BB * KK / NPACK_BLK)        // 2048 elements each

// x bits, transposed: [kw][b]
__device__ uint32_t g_xbitsT[KW * BB];                    // 32 KB
// partial popc sums: [slab][strip][b][OT]
__device__ uint32_t g_partial[SLABS * NSTRIP * BB * OT];  // 4 MB
// grid-internal sync state (self-resetting each launch; zero-init at load)
__device__ int g_pack_done;
__device__ int g_strip_cnt[NSTRIP];
__device__ int g_done;

// Robust 0/1 extraction: int32 {0,1} (bit 0) or float32 {0.0f,1.0f} (bit 23).
__device__ __forceinline__ uint32_t bit01(uint32_t w) {
    return (w | (w >> 23)) & 1u;
}

// ---------------------------------------------------------------------------
// Fused kernel: 1024 blocks (256 strips x 4 slabs) x 256 threads.
//   A (blocks 0..127): ballot-pack a 2048-element slice of x -> g_xbitsT
//   B (all): pack mask slab-strip [1024 k x 16 o] into 2KB bit tile
//   C (all): wait for x bits, XNOR-popcount, store partial sums
//   D (last block per strip): sum 4 slab partials, threshold, write out
// ---------------------------------------------------------------------------
__global__ void __launch_bounds__(256) xnor_fused_kernel(
    const uint32_t* __restrict__ x,       // [BB][KK] 0/1 words
    const uint32_t* __restrict__ masks,   // [KK][OO] 0/1 words
    const int*      __restrict__ thr,     // [OO] int32
    float*          __restrict__ out)     // [BB][OO] float32 0/1
{
    __shared__ uint32_t tile[SKW * OT];   // 2 KB, layout [kw][o]
    __shared__ int s_last;

    const int t     = threadIdx.x;
    const int strip = blockIdx.x & (NSTRIP - 1);
    const int slab  = blockIdx.x >> 8;
    const int o0    = strip * OT;
    const int kw0   = slab * SKW;

    // ---------------- A: x packing (designated blocks, before anything) ----
    if (blockIdx.x < NPACK_BLK) {
        const int base = blockIdx.x * PACK_PER_BLK;
        #pragma unroll
        for (int i = 0; i < PACK_PER_BLK / 256; i++) {
            const int g = base + i * 256 + t;          // (b, k) element id
            const uint32_t v = bit01(x[g]);
            const uint32_t w = __ballot_sync(0xFFFFFFFFu, v);
            if ((t & 31) == 0)
                g_xbitsT[((g & (KK - 1)) >> 5) * BB + (g >> 12)] = w;
        }
        __threadfence();
        __syncthreads();
        if (t == 0) atomicAdd(&g_pack_done, 1);
    }

    // ---------------- B: pack mask slab-strip into shared bits -------------
    // thread -> (op = column pair 0..7, kwl = 0..31)
    {
        const int op  = t & 7;
        const int kwl = t >> 3;
        const uint2* base = reinterpret_cast<const uint2*>(
            masks + (size_t)((kw0 + kwl) * 32) * OO + o0 + op * 2);
        uint32_t a0 = 0, a1 = 0;
        #pragma unroll 8
        for (int j = 0; j < 32; j++) {
            uint2 m = base[(size_t)j * (OO / 2)];
            a0 |= bit01(m.x) << j;
            a1 |= bit01(m.y) << j;
        }
        *reinterpret_cast<uint2*>(&tile[kwl * OT + op * 2]) = make_uint2(a0, a1);
    }
    __syncthreads();

    // ---------------- wait for x bits (long since done: 1MB vs 64MB) -------
    if (t == 0) {
        while (atomicAdd(&g_pack_done, 0) < NPACK_BLK) __nanosleep(64);
        __threadfence();
    }
    __syncthreads();

    // ---------------- C: XNOR popcount over the slab ------------------------
    const int lane = t & 31;
    const int warp = t >> 5;
    const int half = warp & 1;        // which 32 batches
    const int oset = warp >> 1;       // 0..3 -> 4 columns each
    const int b    = half * 32 + lane;

    int acc[4] = {0, 0, 0, 0};
    const uint4* t4 = reinterpret_cast<const uint4*>(tile);

    #pragma unroll
    for (int ck = 0; ck < SKW / 8; ck++) {
        uint32_t xr[8];
        #pragma unroll
        for (int j = 0; j < 8; j++)
            xr[j] = g_xbitsT[(kw0 + ck * 8 + j) * BB + b];

        #pragma unroll
        for (int j = 0; j < 8; j++) {
            const uint32_t xv = xr[j];
            uint4 m = t4[(ck * 8 + j) * 4 + oset];   // broadcast
            acc[0] += __popc(xv ^ m.x);
            acc[1] += __popc(xv ^ m.y);
            acc[2] += __popc(xv ^ m.z);
            acc[3] += __popc(xv ^ m.w);
        }
    }

    // partial store: [slab][strip][b][oset*4..+3]
    uint32_t* pp = &g_partial[(((size_t)slab * NSTRIP + strip) * BB + b) * OT + oset * 4];
    *reinterpret_cast<uint4*>(pp) =
        make_uint4((uint32_t)acc[0], (uint32_t)acc[1],
                   (uint32_t)acc[2], (uint32_t)acc[3]);

    // ---------------- D: last block of this strip reduces + thresholds -----
    __threadfence();
    __syncthreads();
    if (t == 0) {
        int old = atomicAdd(&g_strip_cnt[strip], 1);
        s_last = (old == SLABS - 1);
    }
    __syncthreads();

    if (s_last) {
        if (t == 0) g_strip_cnt[strip] = 0;   // reset for next replay
        __threadfence();                       // acquire partials
        const int o_l = t & 15;
        const int o   = o0 + o_l;
        const int th  = thr[o];
        #pragma unroll
        for (int i = 0; i < 4; i++) {
            const int bb = (t >> 4) + i * 16;
            int s = 0;
            #pragma unroll
            for (int sl = 0; sl < SLABS; sl++)
                s += (int)g_partial[(((size_t)sl * NSTRIP + strip) * BB + bb) * OT + o_l];
            out[(size_t)bb * OO + o] = ((KK - s) > th) ? 1.0f : 0.0f;
        }
    }

    // ---------------- global completion: reset shared counters --------------
    __syncthreads();
    if (t == 0) {
        int old2 = atomicAdd(&g_done, 1);
        if (old2 == GRID - 1) {       // last block anywhere
            g_done = 0;
            g_pack_done = 0;
        }
    }
}

// ---------------------------------------------------------------------------
extern "C" void kernel_launch(void* const* d_in, const int* in_sizes, int n_in,
                              void* d_out, int out_size) {
    // Identify inputs by element count (robust to ordering)
    const void* x     = d_in[0];
    const void* masks = d_in[1];
    const int*  thr   = (const int*)d_in[2];
    for (int i = 0; i < n_in; i++) {
        if      (in_sizes[i] == KK * OO) masks = d_in[i];
        else if (in_sizes[i] == BB * KK) x     = d_in[i];
        else if (in_sizes[i] == OO)      thr   = (const int*)d_in[i];
    }

    xnor_fused_kernel<<<GRID, 256>>>((const uint32_t*)x, (const uint32_t*)masks,
                                     thr, (float*)d_out);
}